// round 10
// baseline (speedup 1.0000x reference)
#include <cuda_runtime.h>

#define TB 32
#define NT 128
#define XS 132
#define HS 264
#define SMEM_FLOATS 28704

__device__ __forceinline__ float sgm(float z){ return 1.0f/(1.0f + __expf(-z)); }

__global__ void __launch_bounds__(NT, 2)
ga_kernel(const float* __restrict__ gx,  const float* __restrict__ g_wr,
          const float* __restrict__ g_an,const float* __restrict__ g_wgp,
          const float* __restrict__ g_wl,const float* __restrict__ g_bl,
          const float* __restrict__ g_wu,const float* __restrict__ g_bu,
          const float* __restrict__ g_aa,const float* __restrict__ g_ba,
          const float* __restrict__ g_wd,const float* __restrict__ g_bd,
          float* __restrict__ gout, int Btot)
{
    extern __shared__ float sm[];
    float* xs   = sm;                 // [32][132]
    float* xrs  = xs  + TB*XS;
    float* atts = xrs + TB*XS;
    float* wr   = atts+ TB*XS;        // [n][slot][4g] 1024
    float* wl   = wr  + 1024;         // 1024
    float* wgp  = wl  + 1024;         // [n][5pg][slot][4p] 5120
    float* wu   = wgp + 5120;         // [m][g][64u] 4096
    float* wd   = wu  + 4096;         // [u][slot][4g] 4096
    float* sn   = wd  + 4096;         // 64
    float* aa   = sn  + 64;           // 256
    float* ba   = aa  + 256;          // 256
    float* blv  = ba  + 256;          // 16
    float* buv  = blv + 16;           // 64
    float* bdv  = buv + 64;           // 16
    float* hs   = xs;                 // alias (x/xr dead in MLP phase)

    const int t = threadIdx.x;
    // slot(m) = (m>>1) | ((m&1)<<3)
    for (int i=t;i<1024;i+=NT){
        int m=i>>6,n=(i>>2)&15,g=i&3;
        int sl=(m>>1)|((m&1)<<3);
        int d=(n*16+sl)*4+g;
        wr[d]=g_wr[i]; wl[d]=g_wl[i];
    }
    for (int i=t;i<5120;i+=NT){
        int m=i/320,n=(i/20)%16,p=i%20;
        int sl=(m>>1)|((m&1)<<3);
        wgp[((n*5+(p>>2))*16+sl)*4+(p&3)]=g_wgp[i];
    }
    for (int i=t;i<4096;i+=NT){int u=i>>6,m=(i>>2)&15,g=i&3;wu[(m*4+g)*64+u]=g_wu[i];}
    for (int i=t;i<4096;i+=NT){
        int m=i>>8,u=(i>>2)&63,g=i&3;
        int sl=(m>>1)|((m&1)<<3);
        wd[(u*16+sl)*4+g]=g_wd[i];
    }
    for (int i=t;i<64;i+=NT){sn[i]=sgm(g_an[i]);buv[i]=g_bu[i];}
    for (int i=t;i<256;i+=NT){aa[i]=g_aa[i];ba[i]=g_ba[i];}
    if (t<16){blv[t]=g_bl[t];bdv[t]=g_bd[t];}

    const int b0 = blockIdx.x * TB;
    for (int i=t;i<TB*32;i+=NT){
        int r=i>>5,c=i&31;
        if (b0+r<Btot) *(float4*)&xs[r*XS+c*4] = ((const float4*)gx)[(size_t)(b0+r)*32+c];
    }
    __syncthreads();

    const int bb = t>>3, q = t&7;     // bb in 0..15; rows bb and bb+16

    // ---------------- Stage A: xr = norm(linear_right(x)) ----------------
    {
        float acc[2][2][8];
        #pragma unroll
        for(int rr=0;rr<2;rr++)
            #pragma unroll
            for(int c=0;c<2;c++)
                #pragma unroll
                for(int j=0;j<8;j++) acc[rr][c][j]=0.f;
        #pragma unroll 4
        for (int n=0;n<16;n++){
            float4 w0=*(const float4*)&wr[(n*16+q)*4];      // m=2q
            float4 w1=*(const float4*)&wr[(n*16+q+8)*4];    // m=2q+1
            #pragma unroll
            for(int rr=0;rr<2;rr++){
                const float* xrow=&xs[(bb+16*rr)*XS];
                float4 xl=*(const float4*)&xrow[n*8];
                float4 xh=*(const float4*)&xrow[n*8+4];
                acc[rr][0][0]=fmaf(xl.x,w0.x,acc[rr][0][0]); acc[rr][1][0]=fmaf(xl.x,w1.x,acc[rr][1][0]);
                acc[rr][0][1]=fmaf(xl.y,w0.y,acc[rr][0][1]); acc[rr][1][1]=fmaf(xl.y,w1.y,acc[rr][1][1]);
                acc[rr][0][2]=fmaf(xl.z,w0.y,acc[rr][0][2]); acc[rr][1][2]=fmaf(xl.z,w1.y,acc[rr][1][2]);
                acc[rr][0][3]=fmaf(xl.w,w0.y,acc[rr][0][3]); acc[rr][1][3]=fmaf(xl.w,w1.y,acc[rr][1][3]);
                acc[rr][0][4]=fmaf(xh.x,w0.z,acc[rr][0][4]); acc[rr][1][4]=fmaf(xh.x,w1.z,acc[rr][1][4]);
                acc[rr][0][5]=fmaf(xh.y,w0.z,acc[rr][0][5]); acc[rr][1][5]=fmaf(xh.y,w1.z,acc[rr][1][5]);
                acc[rr][0][6]=fmaf(xh.z,w0.z,acc[rr][0][6]); acc[rr][1][6]=fmaf(xh.z,w1.z,acc[rr][1][6]);
                acc[rr][0][7]=fmaf(xh.w,w0.w,acc[rr][0][7]); acc[rr][1][7]=fmaf(xh.w,w1.w,acc[rr][1][7]);
            }
        }
        #pragma unroll
        for(int rr=0;rr<2;rr++)
        #pragma unroll
        for (int c=0;c<2;c++){
            int mm=2*q+c;
            float* a = acc[rr][c];
            float n0=fabsf(a[0]);
            float n1=sqrtf(a[1]*a[1]+a[2]*a[2]+a[3]*a[3]);
            float n2=sqrtf(a[4]*a[4]+a[5]*a[5]+a[6]*a[6]);
            float n3=fabsf(a[7]);
            float r0=1.f/(fmaf(sn[mm*4+0],n0-1.f,1.f)+1e-6f);
            float r1=1.f/(fmaf(sn[mm*4+1],n1-1.f,1.f)+1e-6f);
            float r2=1.f/(fmaf(sn[mm*4+2],n2-1.f,1.f)+1e-6f);
            float r3=1.f/(fmaf(sn[mm*4+3],n3-1.f,1.f)+1e-6f);
            *(float4*)&xrs[(bb+16*rr)*XS+mm*8]   = make_float4(a[0]*r0,a[1]*r1,a[2]*r1,a[3]*r1);
            *(float4*)&xrs[(bb+16*rr)*XS+mm*8+4] = make_float4(a[4]*r2,a[5]*r2,a[6]*r2,a[7]*r3);
        }
    }
    __syncthreads();

    // ------- Stage B: attended = (linear_left(x)+b_left + GP(x,xr))/sqrt2 -------
    {
        float at[2][2][8];
        #pragma unroll
        for(int rr=0;rr<2;rr++)
            #pragma unroll
            for(int c=0;c<2;c++){
                at[rr][c][0]=blv[2*q+c];
                #pragma unroll
                for(int j=1;j<8;j++) at[rr][c][j]=0.f;
            }
        #pragma unroll 2
        for (int n=0;n<16;n++){
            float4 l0=*(const float4*)&wl[(n*16+q)*4];
            float4 l1=*(const float4*)&wl[(n*16+q+8)*4];
            float4 P0a=*(const float4*)&wgp[((n*5+0)*16+q)*4];
            float4 P1a=*(const float4*)&wgp[((n*5+1)*16+q)*4];
            float4 P2a=*(const float4*)&wgp[((n*5+2)*16+q)*4];
            float4 P3a=*(const float4*)&wgp[((n*5+3)*16+q)*4];
            float4 P4a=*(const float4*)&wgp[((n*5+4)*16+q)*4];
            float4 P0b=*(const float4*)&wgp[((n*5+0)*16+q+8)*4];
            float4 P1b=*(const float4*)&wgp[((n*5+1)*16+q+8)*4];
            float4 P2b=*(const float4*)&wgp[((n*5+2)*16+q+8)*4];
            float4 P3b=*(const float4*)&wgp[((n*5+3)*16+q+8)*4];
            float4 P4b_=*(const float4*)&wgp[((n*5+4)*16+q+8)*4];
            #pragma unroll
            for(int rr=0;rr<2;rr++){
                const float* xrow=&xs[(bb+16*rr)*XS];
                const float* yrow=&xrs[(bb+16*rr)*XS];
                float4 xl=*(const float4*)&xrow[n*8];
                float4 xh=*(const float4*)&xrow[n*8+4];
                float4 yl=*(const float4*)&yrow[n*8];
                float4 yh=*(const float4*)&yrow[n*8+4];
                float x0=xl.x,x1=xl.y,x2=xl.z,x3=xl.w,x4=xh.x,x5=xh.y,x6=xh.z,x7=xh.w;
                float y0=yl.x,y1=yl.y,y2=yl.z,y3=yl.w,y4=yh.x,y5=yh.y,y6=yh.z,y7=yh.w;
                // left linear
                at[rr][0][0]=fmaf(x0,l0.x,at[rr][0][0]); at[rr][1][0]=fmaf(x0,l1.x,at[rr][1][0]);
                at[rr][0][1]=fmaf(x1,l0.y,at[rr][0][1]); at[rr][1][1]=fmaf(x1,l1.y,at[rr][1][1]);
                at[rr][0][2]=fmaf(x2,l0.y,at[rr][0][2]); at[rr][1][2]=fmaf(x2,l1.y,at[rr][1][2]);
                at[rr][0][3]=fmaf(x3,l0.y,at[rr][0][3]); at[rr][1][3]=fmaf(x3,l1.y,at[rr][1][3]);
                at[rr][0][4]=fmaf(x4,l0.z,at[rr][0][4]); at[rr][1][4]=fmaf(x4,l1.z,at[rr][1][4]);
                at[rr][0][5]=fmaf(x5,l0.z,at[rr][0][5]); at[rr][1][5]=fmaf(x5,l1.z,at[rr][1][5]);
                at[rr][0][6]=fmaf(x6,l0.z,at[rr][0][6]); at[rr][1][6]=fmaf(x6,l1.z,at[rr][1][6]);
                at[rr][0][7]=fmaf(x7,l0.w,at[rr][0][7]); at[rr][1][7]=fmaf(x7,l1.w,at[rr][1][7]);
                // Cayley buckets (44 nonzero (path, out-blade) terms of Cl(3,0))
                float a0=x0*y0,a1=x0*y1,a2=x0*y2,a3=x0*y3,a4=x0*y4,a5=x0*y5,a6=x0*y6,a7=x0*y7;
                float c1=x1*y0,c2=x2*y0,c3=x3*y0,c4=x4*y0,c5=x5*y0,c6=x6*y0,c7=x7*y0;
                float p4b = fmaf(x1,y1,fmaf(x2,y2,x3*y3));
                float p10b=-fmaf(x4,y4,fmaf(x5,y5,x6*y6));
                float p16b=-x7*y7;
                float q1=-fmaf(x2,y4, x3*y5);
                float q2= fmaf(x1,y4,-x3*y6);
                float q3= fmaf(x1,y5, x2*y6);
                float r1= fmaf(x4,y2, x5*y3);
                float r2= fmaf(x6,y3,-x4*y1);
                float r3=-fmaf(x5,y1, x6*y2);
                float s1=-x6*y7, s2= x5*y7, s3=-x4*y7;
                float t1=-x7*y6, t2= x7*y5, t3=-x7*y4;
                float u4= fmaf(x1,y2,-x2*y1);
                float u5= fmaf(x1,y3,-x3*y1);
                float u6= fmaf(x2,y3,-x3*y2);
                float v4= x3*y7, v5=-x2*y7, v6= x1*y7;
                float e4= x7*y3, e5=-x7*y2, e6= x7*y1;
                float m4= fmaf(x6,y5,-x5*y6);
                float m5= fmaf(x4,y6,-x6*y4);
                float m6= fmaf(x5,y4,-x4*y5);
                float z7a=fmaf(x1,y6,fmaf(-x2,y5,x3*y4));
                float z7b=fmaf(x4,y3,fmaf(-x5,y2,x6*y1));
                #pragma unroll
                for(int c=0;c<2;c++){
                    float4 P0=c?P0b:P0a, P1=c?P1b:P1a, P2=c?P2b:P2a, P3=c?P3b:P3a, P4=c?P4b_:P4a;
                    at[rr][c][0]=fmaf(P0.x,a0,fmaf(P1.x,p4b,fmaf(P2.z,p10b,fmaf(P4.x,p16b,at[rr][c][0]))));
                    at[rr][c][1]=fmaf(P0.y,a1,fmaf(P1.y,c1,fmaf(P1.z,q1,fmaf(P2.w,r1,fmaf(P3.x,s1,fmaf(P4.y,t1,at[rr][c][1]))))));
                    at[rr][c][2]=fmaf(P0.y,a2,fmaf(P1.y,c2,fmaf(P1.z,q2,fmaf(P2.w,r2,fmaf(P3.x,s2,fmaf(P4.y,t2,at[rr][c][2]))))));
                    at[rr][c][3]=fmaf(P0.y,a3,fmaf(P1.y,c3,fmaf(P1.z,q3,fmaf(P2.w,r3,fmaf(P3.x,s3,fmaf(P4.y,t3,at[rr][c][3]))))));
                    at[rr][c][4]=fmaf(P0.z,a4,fmaf(P3.y,c4,fmaf(P1.w,u4,fmaf(P2.x,v4,fmaf(P4.z,e4,fmaf(P3.z,m4,at[rr][c][4]))))));
                    at[rr][c][5]=fmaf(P0.z,a5,fmaf(P3.y,c5,fmaf(P1.w,u5,fmaf(P2.x,v5,fmaf(P4.z,e5,fmaf(P3.z,m5,at[rr][c][5]))))));
                    at[rr][c][6]=fmaf(P0.z,a6,fmaf(P3.y,c6,fmaf(P1.w,u6,fmaf(P2.x,v6,fmaf(P4.z,e6,fmaf(P3.z,m6,at[rr][c][6]))))));
                    at[rr][c][7]=fmaf(P0.w,a7,fmaf(P4.w,c7,fmaf(P2.y,z7a,fmaf(P3.w,z7b,at[rr][c][7]))));
                }
            }
        }
        const float RS2=0.70710678118654752440f;
        #pragma unroll
        for(int rr=0;rr<2;rr++)
        #pragma unroll
        for(int c=0;c<2;c++){
            int mm=2*q+c;
            float* a=at[rr][c];
            *(float4*)&atts[(bb+16*rr)*XS+mm*8]   = make_float4(a[0]*RS2,a[1]*RS2,a[2]*RS2,a[3]*RS2);
            *(float4*)&atts[(bb+16*rr)*XS+mm*8+4] = make_float4(a[4]*RS2,a[5]*RS2,a[6]*RS2,a[7]*RS2);
        }
    }
    __syncthreads();

    // ---------------- Stage C: MLP (up -> gate -> down) in 2 u-passes ----------------
    float oacc[2][2][8];
    #pragma unroll
    for(int rr=0;rr<2;rr++)
        #pragma unroll
        for(int c=0;c<2;c++){
            oacc[rr][c][0]=bdv[2*q+c];
            #pragma unroll
            for(int j=1;j<8;j++) oacc[rr][c][j]=0.f;
        }
    #pragma unroll
    for (int pass=0;pass<2;pass++){
        const int u0 = pass*32 + q*4;
        float h[2][4][8];
        #pragma unroll
        for(int rr=0;rr<2;rr++)
            #pragma unroll
            for(int uu=0;uu<4;uu++){
                h[rr][uu][0]=buv[u0+uu];
                #pragma unroll
                for(int j=1;j<8;j++) h[rr][uu][j]=0.f;
            }
        #pragma unroll 2
        for (int m=0;m<16;m++){
            float4 w0=*(const float4*)&wu[(m*4+0)*64+u0];
            float4 w1=*(const float4*)&wu[(m*4+1)*64+u0];
            float4 w2=*(const float4*)&wu[(m*4+2)*64+u0];
            float4 w3=*(const float4*)&wu[(m*4+3)*64+u0];
            float g0[4]={w0.x,w0.y,w0.z,w0.w};
            float g1[4]={w1.x,w1.y,w1.z,w1.w};
            float g2[4]={w2.x,w2.y,w2.z,w2.w};
            float g3[4]={w3.x,w3.y,w3.z,w3.w};
            #pragma unroll
            for(int rr=0;rr<2;rr++){
                const float* arow=&atts[(bb+16*rr)*XS];
                float4 al=*(const float4*)&arow[m*8];
                float4 ah=*(const float4*)&arow[m*8+4];
                #pragma unroll
                for(int uu=0;uu<4;uu++){
                    h[rr][uu][0]=fmaf(al.x,g0[uu],h[rr][uu][0]);
                    h[rr][uu][1]=fmaf(al.y,g1[uu],h[rr][uu][1]);
                    h[rr][uu][2]=fmaf(al.z,g1[uu],h[rr][uu][2]);
                    h[rr][uu][3]=fmaf(al.w,g1[uu],h[rr][uu][3]);
                    h[rr][uu][4]=fmaf(ah.x,g2[uu],h[rr][uu][4]);
                    h[rr][uu][5]=fmaf(ah.y,g2[uu],h[rr][uu][5]);
                    h[rr][uu][6]=fmaf(ah.z,g2[uu],h[rr][uu][6]);
                    h[rr][uu][7]=fmaf(ah.w,g3[uu],h[rr][uu][7]);
                }
            }
        }
        #pragma unroll
        for(int rr=0;rr<2;rr++)
        #pragma unroll
        for(int uu=0;uu<4;uu++){
            int u=u0+uu;
            float* hv=h[rr][uu];
            float i0=hv[0];
            float i1=fmaf(hv[1],hv[1],fmaf(hv[2],hv[2],hv[3]*hv[3]));
            float i2=fmaf(hv[4],hv[4],fmaf(hv[5],hv[5],hv[6]*hv[6]));
            float i3=hv[7]*hv[7];
            float ga=sgm(fmaf(aa[u*4+0],i0,ba[u*4+0]));
            float gb=sgm(fmaf(aa[u*4+1],i1,ba[u*4+1]));
            float gc=sgm(fmaf(aa[u*4+2],i2,ba[u*4+2]));
            float gd=sgm(fmaf(aa[u*4+3],i3,ba[u*4+3]));
            int slot=uu*8+q;
            *(float4*)&hs[(bb+16*rr)*HS+slot*8]   = make_float4(hv[0]*ga,hv[1]*gb,hv[2]*gb,hv[3]*gb);
            *(float4*)&hs[(bb+16*rr)*HS+slot*8+4] = make_float4(hv[4]*gc,hv[5]*gc,hv[6]*gc,hv[7]*gd);
        }
        __syncthreads();
        #pragma unroll 2
        for (int s=0;s<32;s++){
            int u = pass*32 + ((s&7)<<2) + (s>>3);
            float4 d0=*(const float4*)&wd[(u*16+q)*4];      // m=2q
            float4 d1=*(const float4*)&wd[(u*16+q+8)*4];    // m=2q+1
            #pragma unroll
            for(int rr=0;rr<2;rr++){
                float4 hl=*(const float4*)&hs[(bb+16*rr)*HS+s*8];
                float4 hh=*(const float4*)&hs[(bb+16*rr)*HS+s*8+4];
                oacc[rr][0][0]=fmaf(hl.x,d0.x,oacc[rr][0][0]); oacc[rr][1][0]=fmaf(hl.x,d1.x,oacc[rr][1][0]);
                oacc[rr][0][1]=fmaf(hl.y,d0.y,oacc[rr][0][1]); oacc[rr][1][1]=fmaf(hl.y,d1.y,oacc[rr][1][1]);
                oacc[rr][0][2]=fmaf(hl.z,d0.y,oacc[rr][0][2]); oacc[rr][1][2]=fmaf(hl.z,d1.y,oacc[rr][1][2]);
                oacc[rr][0][3]=fmaf(hl.w,d0.y,oacc[rr][0][3]); oacc[rr][1][3]=fmaf(hl.w,d1.y,oacc[rr][1][3]);
                oacc[rr][0][4]=fmaf(hh.x,d0.z,oacc[rr][0][4]); oacc[rr][1][4]=fmaf(hh.x,d1.z,oacc[rr][1][4]);
                oacc[rr][0][5]=fmaf(hh.y,d0.z,oacc[rr][0][5]); oacc[rr][1][5]=fmaf(hh.y,d1.z,oacc[rr][1][5]);
                oacc[rr][0][6]=fmaf(hh.z,d0.z,oacc[rr][0][6]); oacc[rr][1][6]=fmaf(hh.z,d1.z,oacc[rr][1][6]);
                oacc[rr][0][7]=fmaf(hh.w,d0.w,oacc[rr][0][7]); oacc[rr][1][7]=fmaf(hh.w,d1.w,oacc[rr][1][7]);
            }
        }
        __syncthreads();
    }

    const int b0r = blockIdx.x * TB;
    #pragma unroll
    for(int rr=0;rr<2;rr++){
        int row = bb + 16*rr;
        if (b0r + row < Btot){
            const float* arow=&atts[row*XS];
            #pragma unroll
            for(int c=0;c<2;c++){
                int mm=2*q+c;
                float4 al=*(const float4*)&arow[mm*8];
                float4 ah=*(const float4*)&arow[mm*8+4];
                size_t o=(size_t)(b0r+row)*128 + mm*8;
                float* oa=oacc[rr][c];
                *(float4*)&gout[o]   = make_float4(al.x+oa[0],al.y+oa[1],al.z+oa[2],al.w+oa[3]);
                *(float4*)&gout[o+4] = make_float4(ah.x+oa[4],ah.y+oa[5],ah.z+oa[6],ah.w+oa[7]);
            }
        }
    }
}

extern "C" void kernel_launch(void* const* d_in, const int* in_sizes, int n_in,
                              void* d_out, int out_size)
{
    const float* x    = (const float*)d_in[0];
    const float* wr   = (const float*)d_in[1];
    const float* an   = (const float*)d_in[2];
    const float* wgp  = (const float*)d_in[3];
    const float* wl   = (const float*)d_in[4];
    const float* bl   = (const float*)d_in[5];
    const float* wu   = (const float*)d_in[6];
    const float* bu   = (const float*)d_in[7];
    const float* aact = (const float*)d_in[8];
    const float* bact = (const float*)d_in[9];
    const float* wd   = (const float*)d_in[10];
    const float* bd   = (const float*)d_in[11];

    int Btot = in_sizes[0] / 128;
    int grid = (Btot + TB - 1) / TB;
    size_t smem = SMEM_FLOATS * sizeof(float);
    cudaFuncSetAttribute(ga_kernel, cudaFuncAttributeMaxDynamicSharedMemorySize, (int)smem);
    ga_kernel<<<grid, NT, smem>>>(x, wr, an, wgp, wl, bl, wu, bu, aact, bact, wd, bd,
                                  (float*)d_out, Btot);
}